// round 10
// baseline (speedup 1.0000x reference)
#include <cuda_runtime.h>
#include <math.h>

// Problem constants
#define BB   32
#define SS   1024
#define DD   3
#define NF   512
#define NS   64
#define HID  100
#define FSZ  256

// Decomposition
#define NSC  16           // S chunks
#define SCH  (SS/NSC)     // 64 steps per chunk

// Scratch (device globals: allocation-free per harness rules)
__device__ float g_Womg[NF*3];
__device__ float g_totC[BB*NSC*NF];
__device__ float g_totS[BB*NSC*NF];

// Warp-wide float add reduction (SHFL butterfly; redux.f32 unavailable on
// the compute_103 PTX target).
__device__ __forceinline__ float warp_sum(float v) {
    #pragma unroll
    for (int o = 16; o; o >>= 1) v += __shfl_xor_sync(0xffffffffu, v, o);
    return v;
}

// ---------------- Fused Fourier-feature MLP ----------------
// R6-proven structure: one block per fourier sample f, 128 threads, each
// thread owns fourier columns (t, t+128) -> two independent FMA chains.
// Measured <=5.4us in round 6; do not "improve" without evidence.

__global__ void __launch_bounds__(128) k_mlp(const float* __restrict__ noise,
                                             const float* __restrict__ W1,
                                             const float* __restrict__ b1,
                                             const float* __restrict__ W2,
                                             const float* __restrict__ b2,
                                             const float* __restrict__ W) {
    int f = blockIdx.x;
    int t = threadIdx.x;

    __shared__ float s_noise[NS];
    __shared__ float s_h[HID];
    __shared__ float s_red[4][3];

    if (t < NS) s_noise[t] = noise[f*NS + t];
    __syncthreads();

    // hidden: h[j] = tanh(b1[j] + sum_k noise[k] * W1[k,j])
    if (t < HID) {
        float acc = b1[t];
        #pragma unroll 8
        for (int k = 0; k < NS; k++)
            acc = fmaf(s_noise[k], W1[k*HID + t], acc);
        s_h[t] = tanhf(acc);
    }
    __syncthreads();

    // fourier: fs[i] = tanh(b2[i] + sum_j h[j] * W2[j,i]); 2 i's per thread
    int i0 = t, i1 = t + 128;
    float a0 = b2[i0], a1 = b2[i1];
    #pragma unroll 4
    for (int j = 0; j < HID; j++) {
        float h = s_h[j];
        a0 = fmaf(h, W2[j*FSZ + i0], a0);
        a1 = fmaf(h, W2[j*FSZ + i1], a1);
    }
    float fs0 = tanhf(a0), fs1 = tanhf(a1);

    // Womg[f][d] = sum_i fs[i] * W[i,d]
    float p0 = fmaf(fs0, W[i0*3+0], fs1*W[i1*3+0]);
    float p1 = fmaf(fs0, W[i0*3+1], fs1*W[i1*3+1]);
    float p2 = fmaf(fs0, W[i0*3+2], fs1*W[i1*3+2]);
    p0 = warp_sum(p0); p1 = warp_sum(p1); p2 = warp_sum(p2);
    int lane = t & 31, warp = t >> 5;
    if (lane == 0) { s_red[warp][0] = p0; s_red[warp][1] = p1; s_red[warp][2] = p2; }
    __syncthreads();
    if (t < 3) {
        float v = s_red[0][t] + s_red[1][t] + s_red[2][t] + s_red[3][t];
        g_Womg[f*3 + t] = v;
    }
}

// ---------------- Pass A: per-S-chunk trig totals ----------------
// 512 threads = all NF features; grid (NSC, BB).

__global__ void __launch_bounds__(512) k_passA(const float* __restrict__ X) {
    int t  = threadIdx.x;            // n = t
    int sc = blockIdx.x, b = blockIdx.y;
    float w0 = g_Womg[t*3+0], w1 = g_Womg[t*3+1], w2 = g_Womg[t*3+2];

    __shared__ float sx[SCH*3];
    int s0 = sc*SCH;
    const float* xp = X + ((size_t)b*SS + s0)*3;
    if (t < SCH*3) sx[t] = xp[t];
    __syncthreads();

    float sumC = 0.f, sumS = 0.f;
    #pragma unroll 8
    for (int k = 0; k < SCH; k++) {
        float th = fmaf(sx[k*3+2], w2, fmaf(sx[k*3+1], w1, sx[k*3]*w0));
        float sv, cv;
        __sincosf(th, &sv, &cv);
        sumC += cv; sumS += sv;
    }
    g_totC[(b*NSC + sc)*NF + t] = sumC;
    g_totS[(b*NSC + sc)*NF + t] = sumS;
}

// ---------------- Pass C fused with final output ----------------
// Same grid/block as passA. All 16 warp-partials per step stay in smem;
// block reduces them and writes lam + loglik directly.

__global__ void __launch_bounds__(512) k_passCF(const float* __restrict__ X,
                                                const float* __restrict__ alpha,
                                                float* __restrict__ out) {
    int t  = threadIdx.x;            // n = t
    int sc = blockIdx.x, b = blockIdx.y;
    float w0 = g_Womg[t*3+0], w1 = g_Womg[t*3+1], w2 = g_Womg[t*3+2];

    // exclusive offsets from preceding S chunks
    float runC = 0.f, runS = 0.f;
    for (int p = 0; p < sc; p++) {
        runC += g_totC[(b*NSC + p)*NF + t];
        runS += g_totS[(b*NSC + p)*NF + t];
    }

    __shared__ float sx[SCH*3];
    __shared__ float s_red[SCH][17];   // +1 pad: conflict-free tail reads
    int s0 = sc*SCH;
    const float* xp = X + ((size_t)b*SS + s0)*3;
    if (t < SCH*3) sx[t] = xp[t];
    __syncthreads();

    int lane = t & 31, warp = t >> 5;

    #pragma unroll 4
    for (int k = 0; k < SCH; k++) {
        float th = fmaf(sx[k*3+2], w2, fmaf(sx[k*3+1], w1, sx[k*3]*w0));
        float sv, cv;
        __sincosf(th, &sv, &cv);
        float contrib = cv*runC + sv*runS;   // EXCLUSIVE prefix
        runC += cv; runS += sv;
        contrib = warp_sum(contrib);
        if (lane == 0) s_red[k][warp] = contrib;
    }
    __syncthreads();

    if (t < SCH) {
        float s = 0.f;
        #pragma unroll
        for (int i = 0; i < 16; i++) s += s_red[t][i];
        float lam = fmaf(alpha[0], s * (1.0f/NF), 10.0f);
        int sg = s0 + t;
        out[b*SS + sg] = lam;

        float x0 = sx[t*3];
        float mask = (x0 > 0.f) ? 1.f : 0.f;
        const float C2 = -3947.8417604357433f;   // -MU*T*(2*pi)^(D-1)
        out[BB*SS + b*(SS+1) + sg] = logf(lam)*mask + C2;
    }
    if (sc == 0 && t == 0) {
        const float C2 = -3947.8417604357433f;
        out[BB*SS + b*(SS+1) + SS] = C2;         // extra (S+1)-th column
    }
}

// ---------------- Launch ----------------

extern "C" void kernel_launch(void* const* d_in, const int* in_sizes, int n_in,
                              void* d_out, int out_size) {
    const float* X     = (const float*)d_in[0];
    const float* noise = (const float*)d_in[1];
    const float* W1    = (const float*)d_in[2];
    const float* b1    = (const float*)d_in[3];
    const float* W2    = (const float*)d_in[4];
    const float* b2    = (const float*)d_in[5];
    const float* W     = (const float*)d_in[6];
    const float* alpha = (const float*)d_in[7];
    float* out = (float*)d_out;

    k_mlp<<<NF, 128>>>(noise, W1, b1, W2, b2, W);

    dim3 grid(NSC, BB);
    k_passA <<<grid, 512>>>(X);
    k_passCF<<<grid, 512>>>(X, alpha, out);
}

// round 11
// speedup vs baseline: 1.0502x; 1.0502x over previous
#include <cuda_runtime.h>
#include <math.h>

// Problem constants
#define BB   32
#define SS   1024
#define DD   3
#define NF   512
#define NS   64
#define HID  100
#define FSZ  256

// Decomposition
#define NSC  16           // S chunks
#define SCH  (SS/NSC)     // 64 steps per chunk

// Scratch (device globals: allocation-free per harness rules)
__device__ float g_Womg[NF*3];
__device__ float g_totC[BB*NSC*NF];
__device__ float g_totS[BB*NSC*NF];

// Warp-wide float add reduction (SHFL butterfly; redux.f32 unavailable on
// the compute_103 PTX target).
__device__ __forceinline__ float warp_sum(float v) {
    #pragma unroll
    for (int o = 16; o; o >>= 1) v += __shfl_xor_sync(0xffffffffu, v, o);
    return v;
}

// ---------------- Fused Fourier-feature MLP ----------------
// Latency/occupancy-bound (ncu R9: DRAM 0.3%, L2 2.7%, occ 41.6% grid-capped).
// Fix: 512 threads/block via j-split. Thread (col = t&255, jhalf = t>>8)
// computes a 50-step partial of the fourier dot (2 sub-accumulators);
// halves combine through smem. Hidden layer k-split the same way.
// 512 blocks x 16 warps = 8192 warps -> ~55 warps/SM (86% occ), and the
// longest dependent FMA chain drops 100 -> 25.

__global__ void __launch_bounds__(512) k_mlp(const float* __restrict__ noise,
                                             const float* __restrict__ W1,
                                             const float* __restrict__ b1,
                                             const float* __restrict__ W2,
                                             const float* __restrict__ b2,
                                             const float* __restrict__ W) {
    int f = blockIdx.x;
    int t = threadIdx.x;
    int tl   = t & 255;      // col / hidden-unit id
    int half = t >> 8;       // 0 or 1: which j/k half this thread owns

    __shared__ float s_noise[NS];
    __shared__ float s_hp[2][HID];    // hidden k-partials
    __shared__ float s_h[HID];
    __shared__ float s_acc[512];      // fourier j-partials
    __shared__ float s_red[8][3];

    if (t < NS) s_noise[t] = noise[f*NS + t];
    __syncthreads();

    // hidden partials: h[j] over k in [half*32, half*32+32)
    if (tl < HID) {
        int k0 = half * 32;
        float a0 = 0.f, a1 = 0.f;
        #pragma unroll 8
        for (int k = 0; k < 32; k += 2) {
            a0 = fmaf(s_noise[k0+k],   W1[(k0+k)*HID + tl],   a0);
            a1 = fmaf(s_noise[k0+k+1], W1[(k0+k+1)*HID + tl], a1);
        }
        s_hp[half][tl] = a0 + a1;
    }
    __syncthreads();
    if (t < HID)
        s_h[t] = tanhf(b1[t] + s_hp[0][t] + s_hp[1][t]);
    __syncthreads();

    // fourier partials: col = tl, j in [half*50, half*50+50)
    {
        int jb = half * 50;
        float a0 = 0.f, a1 = 0.f;
        #pragma unroll 5
        for (int j = 0; j < 50; j += 2) {
            a0 = fmaf(s_h[jb+j],   W2[(jb+j)*FSZ + tl],   a0);
            a1 = fmaf(s_h[jb+j+1], W2[(jb+j+1)*FSZ + tl], a1);
        }
        s_acc[t] = a0 + a1;
    }
    __syncthreads();

    // combine halves, tanh, Womg reduction (threads 0..255 = warps 0..7)
    if (t < 256) {
        float fs = tanhf(b2[t] + s_acc[t] + s_acc[t + 256]);
        float p0 = fs * W[t*3+0];
        float p1 = fs * W[t*3+1];
        float p2 = fs * W[t*3+2];
        p0 = warp_sum(p0); p1 = warp_sum(p1); p2 = warp_sum(p2);
        int lane = t & 31, warp = t >> 5;
        if (lane == 0) {
            s_red[warp][0] = p0; s_red[warp][1] = p1; s_red[warp][2] = p2;
        }
    }
    __syncthreads();
    if (t < 3) {
        float v = 0.f;
        #pragma unroll
        for (int w = 0; w < 8; w++) v += s_red[w][t];
        g_Womg[f*3 + t] = v;
    }
}

// ---------------- Pass A: per-S-chunk trig totals ----------------
// 512 threads = all NF features; grid (NSC, BB).

__global__ void __launch_bounds__(512) k_passA(const float* __restrict__ X) {
    int t  = threadIdx.x;            // n = t
    int sc = blockIdx.x, b = blockIdx.y;
    float w0 = g_Womg[t*3+0], w1 = g_Womg[t*3+1], w2 = g_Womg[t*3+2];

    __shared__ float sx[SCH*3];
    int s0 = sc*SCH;
    const float* xp = X + ((size_t)b*SS + s0)*3;
    if (t < SCH*3) sx[t] = xp[t];
    __syncthreads();

    float sumC = 0.f, sumS = 0.f;
    #pragma unroll 8
    for (int k = 0; k < SCH; k++) {
        float th = fmaf(sx[k*3+2], w2, fmaf(sx[k*3+1], w1, sx[k*3]*w0));
        float sv, cv;
        __sincosf(th, &sv, &cv);
        sumC += cv; sumS += sv;
    }
    g_totC[(b*NSC + sc)*NF + t] = sumC;
    g_totS[(b*NSC + sc)*NF + t] = sumS;
}

// ---------------- Pass C fused with final output ----------------
// Same grid/block as passA. All 16 warp-partials per step stay in smem;
// block reduces them and writes lam + loglik directly.

__global__ void __launch_bounds__(512) k_passCF(const float* __restrict__ X,
                                                const float* __restrict__ alpha,
                                                float* __restrict__ out) {
    int t  = threadIdx.x;            // n = t
    int sc = blockIdx.x, b = blockIdx.y;
    float w0 = g_Womg[t*3+0], w1 = g_Womg[t*3+1], w2 = g_Womg[t*3+2];

    // exclusive offsets from preceding S chunks
    float runC = 0.f, runS = 0.f;
    for (int p = 0; p < sc; p++) {
        runC += g_totC[(b*NSC + p)*NF + t];
        runS += g_totS[(b*NSC + p)*NF + t];
    }

    __shared__ float sx[SCH*3];
    __shared__ float s_red[SCH][17];   // +1 pad: conflict-free tail reads
    int s0 = sc*SCH;
    const float* xp = X + ((size_t)b*SS + s0)*3;
    if (t < SCH*3) sx[t] = xp[t];
    __syncthreads();

    int lane = t & 31, warp = t >> 5;

    #pragma unroll 4
    for (int k = 0; k < SCH; k++) {
        float th = fmaf(sx[k*3+2], w2, fmaf(sx[k*3+1], w1, sx[k*3]*w0));
        float sv, cv;
        __sincosf(th, &sv, &cv);
        float contrib = cv*runC + sv*runS;   // EXCLUSIVE prefix
        runC += cv; runS += sv;
        contrib = warp_sum(contrib);
        if (lane == 0) s_red[k][warp] = contrib;
    }
    __syncthreads();

    if (t < SCH) {
        float s = 0.f;
        #pragma unroll
        for (int i = 0; i < 16; i++) s += s_red[t][i];
        float lam = fmaf(alpha[0], s * (1.0f/NF), 10.0f);
        int sg = s0 + t;
        out[b*SS + sg] = lam;

        float x0 = sx[t*3];
        float mask = (x0 > 0.f) ? 1.f : 0.f;
        const float C2 = -3947.8417604357433f;   // -MU*T*(2*pi)^(D-1)
        out[BB*SS + b*(SS+1) + sg] = logf(lam)*mask + C2;
    }
    if (sc == 0 && t == 0) {
        const float C2 = -3947.8417604357433f;
        out[BB*SS + b*(SS+1) + SS] = C2;         // extra (S+1)-th column
    }
}

// ---------------- Launch ----------------

extern "C" void kernel_launch(void* const* d_in, const int* in_sizes, int n_in,
                              void* d_out, int out_size) {
    const float* X     = (const float*)d_in[0];
    const float* noise = (const float*)d_in[1];
    const float* W1    = (const float*)d_in[2];
    const float* b1    = (const float*)d_in[3];
    const float* W2    = (const float*)d_in[4];
    const float* b2    = (const float*)d_in[5];
    const float* W     = (const float*)d_in[6];
    const float* alpha = (const float*)d_in[7];
    float* out = (float*)d_out;

    k_mlp<<<NF, 512>>>(noise, W1, b1, W2, b2, W);

    dim3 grid(NSC, BB);
    k_passA <<<grid, 512>>>(X);
    k_passCF<<<grid, 512>>>(X, alpha, out);
}